// round 13
// baseline (speedup 1.0000x reference)
#include <cuda_runtime.h>
#include <cuda_fp16.h>

// RoIMaskAlign via NHWC-fp16 staging, round 13: vectorized transpose reads,
// per-sample tap guards, hoisted lane offset.
// features (B=2, C=256, H=200, W=272) fp32, rois (K, 5) fp32
// out (K, C, 14, 14) fp32

#define PH 14
#define PW 14

static constexpr int   Bc = 2;
static constexpr int   Cc = 256;
static constexpr int   Hc = 200;
static constexpr int   Wc = 272;
static constexpr float SCALE     = 0.25f;
static constexpr float ROI_SCALE = 1.2f;

// NHWC fp16 scratch: (B, H, W, C) = 2*200*272*256 halves = 55.7 MB
__device__ __align__(16) __half g_nhwc[(size_t)Bc * Hc * Wc * Cc];

// ---------------------------------------------------------------------------
// Kernel 1: NCHW fp32 -> NHWC fp16 transpose. float4 reads (4 LDG.128/thread),
// __ldcs evict-first so L2 is kept for the NHWC table.
// ---------------------------------------------------------------------------
__global__ __launch_bounds__(256)
void transpose_kernel(const float* __restrict__ feat)
{
    __shared__ __align__(16) __half s[16][264];   // [x][c]

    int x0 = blockIdx.x * 16;
    int y  = blockIdx.y;
    int b  = blockIdx.z;
    int tid = threadIdx.x;
    int q     = tid & 3;          // x-quad: x = 4q..4q+3
    int cbase = tid >> 2;         // 0..63

    const float* fp = feat + ((size_t)(b * Cc + cbase) * Hc + y) * Wc + x0 + 4 * q;
    #pragma unroll
    for (int k = 0; k < 4; k++) {
        int c = cbase + 64 * k;
        float4 v = __ldcs(reinterpret_cast<const float4*>(fp + (size_t)(64 * k) * (Hc * Wc)));
        s[4 * q + 0][c] = __float2half_rn(v.x);
        s[4 * q + 1][c] = __float2half_rn(v.y);
        s[4 * q + 2][c] = __float2half_rn(v.z);
        s[4 * q + 3][c] = __float2half_rn(v.w);
    }
    __syncthreads();

    __half* op = g_nhwc + (((size_t)b * Hc + y) * Wc + x0) * Cc;
    #pragma unroll
    for (int j = 0; j < 2; j++) {
        int u = tid + j * 256;
        int x = u >> 5;
        int k = u & 31;
        *reinterpret_cast<uint4*>(op + (size_t)x * Cc + k * 8) =
            *reinterpret_cast<const uint4*>(&s[x][k * 8]);
    }
}

// ---------------------------------------------------------------------------
// Kernel 2: gather. Block = (n, php), php = ph/2; 14 warps (448 thr).
// Warp w: ph_local = w/7, pw = (w%7)*2 + {0,1}. Lane owns 8 channels.
// HFMA2 tap math; per-sample guard -> 4 tap loads batch back-to-back.
// ---------------------------------------------------------------------------
static constexpr int BINS = 28;
static constexpr int SSTR = 260;

__global__ __launch_bounds__(448, 2)
void gather_kernel(const float* __restrict__ rois,
                   float* __restrict__ out)
{
    __shared__ __align__(16) float s[BINS * SSTR];   // 29120 B

    int n   = blockIdx.x;
    int php = blockIdx.y;            // 0..6
    int wid  = threadIdx.x >> 5;     // 0..13
    int lane = threadIdx.x & 31;
    int ph_l   = wid / 7;            // 0..1
    int pwpair = wid % 7;            // 0..6
    int ph  = php * 2 + ph_l;

    const float* r = rois + n * 5;
    int   b  = (int)r[0];
    float rx1 = r[1], ry1 = r[2], rx2 = r[3], ry2 = r[4];

    float cx = (rx1 + rx2) * 0.5f;
    float cy = (ry1 + ry2) * 0.5f;
    float rw = (rx2 - rx1) * ROI_SCALE;
    float rh = (ry2 - ry1) * ROI_SCALE;
    float x1s = (cx - 0.5f * rw) * SCALE;
    float x2s = (cx + 0.5f * rw) * SCALE;
    float y1s = (cy - 0.5f * rh) * SCALE;
    float y2s = (cy + 0.5f * rh) * SCALE;

    float roi_w = fmaxf(x2s - x1s, 1.0f);
    float roi_h = fmaxf(y2s - y1s, 1.0f);
    float bin_w = roi_w * (1.0f / PW);
    float bin_h = roi_h * (1.0f / PH);

    // lane offset hoisted once
    const __half* tbl = g_nhwc + (size_t)lane * 8;

    #pragma unroll
    for (int i = 0; i < 2; i++) {
        int pw  = pwpair * 2 + i;
        int bin = ph_l * PW + pw;

        float a0=0.f,a1=0.f,a2=0.f,a3=0.f,a4=0.f,a5=0.f,a6=0.f,a7=0.f;

        int   xi0[2], xi1[2];
        float lx[2], hx[2];
        bool  vx[2];
        #pragma unroll
        for (int sx = 0; sx < 2; sx++) {
            float x = x1s + ((float)pw + ((float)sx + 0.5f) * 0.5f) * bin_w;
            vx[sx] = (x > -1.0f) && (x < (float)Wc);
            float xc = fminf(fmaxf(x, 0.0f), (float)(Wc - 1));
            int x0 = (int)floorf(xc);
            xi0[sx] = x0;
            xi1[sx] = min(x0 + 1, Wc - 1);
            lx[sx] = xc - (float)x0;
            hx[sx] = 1.0f - lx[sx];
        }

        // HFMA2 tap: 1 cvt + 4 HFMA2 (no guard: caller guards per sample)
        #define TAP(pix, wt) do {                                               \
            uint4 v = *reinterpret_cast<const uint4*>(                          \
                tbl + (((size_t)(pix)) << 8));                                  \
            const __half2* hp = reinterpret_cast<const __half2*>(&v);           \
            __half2 wh = __float2half2_rn(wt);                                  \
            h0 = __hfma2(wh, hp[0], h0);                                        \
            h1 = __hfma2(wh, hp[1], h1);                                        \
            h2 = __hfma2(wh, hp[2], h2);                                        \
            h3 = __hfma2(wh, hp[3], h3);                                        \
        } while (0)

        #pragma unroll
        for (int sy = 0; sy < 2; sy++) {
            float y = y1s + ((float)ph + (sy ? 0.75f : 0.25f)) * bin_h;
            bool vy = (y > -1.0f) && (y < (float)Hc);
            float yc = fminf(fmaxf(y, 0.0f), (float)(Hc - 1));
            int y0 = (int)floorf(yc);
            int y1b = min(y0 + 1, Hc - 1);
            float ly = yc - (float)y0;
            float hy = 1.0f - ly;

            int rb0 = (b * Hc + y0)  * Wc;
            int rb1 = (b * Hc + y1b) * Wc;

            __half2 h0 = __float2half2_rn(0.f);
            __half2 h1 = h0, h2 = h0, h3 = h0;

            #pragma unroll
            for (int sx = 0; sx < 2; sx++) {
                if (vy && vx[sx]) {           // warp-uniform, per sample
                    float wq  = 0.25f;        // mean folded
                    float w00 = wq * hy * hx[sx];
                    float w01 = wq * hy * lx[sx];
                    float w10 = wq * ly * hx[sx];
                    float w11 = wq * ly * lx[sx];
                    TAP(rb0 + xi0[sx], w00);
                    TAP(rb0 + xi1[sx], w01);
                    TAP(rb1 + xi0[sx], w10);
                    TAP(rb1 + xi1[sx], w11);
                }
            }

            float2 f0 = __half22float2(h0);
            float2 f1 = __half22float2(h1);
            float2 f2 = __half22float2(h2);
            float2 f3 = __half22float2(h3);
            a0 += f0.x; a1 += f0.y;
            a2 += f1.x; a3 += f1.y;
            a4 += f2.x; a5 += f2.y;
            a6 += f3.x; a7 += f3.y;
        }
        #undef TAP

        float* dst = s + bin * SSTR + lane * 8;
        *reinterpret_cast<float4*>(dst)     = make_float4(a0, a1, a2, a3);
        *reinterpret_cast<float4*>(dst + 4) = make_float4(a4, a5, a6, a7);
    }

    __syncthreads();

    for (int c = wid; c < Cc; c += 14) {
        if (lane < BINS) {
            __stcs(out + ((size_t)n * Cc + c) * (PH * PW) + php * BINS + lane,
                   s[lane * SSTR + c]);
        }
    }
}

extern "C" void kernel_launch(void* const* d_in, const int* in_sizes, int n_in,
                              void* d_out, int out_size)
{
    const float* feat = (const float*)d_in[0];
    const float* rois = (const float*)d_in[1];
    float* out = (float*)d_out;

    int K = in_sizes[1] / 5;

    dim3 tg(Wc / 16, Hc, Bc);          // 17 x 200 x 2
    transpose_kernel<<<tg, 256>>>(feat);

    dim3 gg(K, PH / 2);                // K x 7
    gather_kernel<<<gg, 448>>>(rois, out);
}

// round 14
// speedup vs baseline: 1.0430x; 1.0430x over previous
#include <cuda_runtime.h>
#include <cuda_fp16.h>

// RoIMaskAlign via NHWC-fp16 staging, round 14: exact R12 core + 32-bit tap
// offsets + LDS.64 epilogue.
// features (B=2, C=256, H=200, W=272) fp32, rois (K, 5) fp32
// out (K, C, 14, 14) fp32

#define PH 14
#define PW 14

static constexpr int   Bc = 2;
static constexpr int   Cc = 256;
static constexpr int   Hc = 200;
static constexpr int   Wc = 272;
static constexpr float SCALE     = 0.25f;
static constexpr float ROI_SCALE = 1.2f;

// NHWC fp16 scratch: (B, H, W, C) = 2*200*272*256 halves = 55.7 MB
__device__ __align__(16) __half g_nhwc[(size_t)Bc * Hc * Wc * Cc];

// ---------------------------------------------------------------------------
// Kernel 1: NCHW fp32 -> NHWC fp16 transpose (R12 version, DRAM-pinned).
// ---------------------------------------------------------------------------
__global__ __launch_bounds__(256)
void transpose_kernel(const float* __restrict__ feat)
{
    __shared__ __align__(16) __half s[16][264];

    int x0 = blockIdx.x * 16;
    int y  = blockIdx.y;
    int b  = blockIdx.z;
    int tid = threadIdx.x;
    int xl = tid & 15;
    int ci = tid >> 4;

    const float* fp = feat + (((size_t)b * Cc) * Hc + y) * Wc + x0 + xl;
    #pragma unroll
    for (int k = 0; k < 16; k++) {
        int c = k * 16 + ci;
        s[xl][c] = __float2half_rn(__ldcs(fp + (size_t)c * (Hc * Wc)));
    }
    __syncthreads();

    __half* op = g_nhwc + (((size_t)b * Hc + y) * Wc + x0) * Cc;
    #pragma unroll
    for (int j = 0; j < 2; j++) {
        int u = tid + j * 256;
        int x = u >> 5;
        int k = u & 31;
        *reinterpret_cast<uint4*>(op + (size_t)x * Cc + k * 8) =
            *reinterpret_cast<const uint4*>(&s[x][k * 8]);
    }
}

// ---------------------------------------------------------------------------
// Kernel 2: gather (R12 structure). Block = (n, php); 14 warps. Warp w:
// ph_local = w/7, pw = (w%7)*2 + {0,1}. Lane owns 8 channels. HFMA2 taps,
// per-tap wt!=0 guard (best measured). 32-bit byte offsets into the table.
// ---------------------------------------------------------------------------
static constexpr int BINS = 28;
static constexpr int SSTR = 260;

__global__ __launch_bounds__(448, 2)
void gather_kernel(const float* __restrict__ rois,
                   float* __restrict__ out)
{
    __shared__ __align__(16) float s[BINS * SSTR];   // 29120 B

    int n   = blockIdx.x;
    int php = blockIdx.y;            // 0..6
    int wid  = threadIdx.x >> 5;     // 0..13
    int lane = threadIdx.x & 31;
    int ph_l   = wid / 7;            // 0..1
    int pwpair = wid % 7;            // 0..6
    int ph  = php * 2 + ph_l;

    const float* r = rois + n * 5;
    int   b  = (int)r[0];
    float rx1 = r[1], ry1 = r[2], rx2 = r[3], ry2 = r[4];

    float cx = (rx1 + rx2) * 0.5f;
    float cy = (ry1 + ry2) * 0.5f;
    float rw = (rx2 - rx1) * ROI_SCALE;
    float rh = (ry2 - ry1) * ROI_SCALE;
    float x1s = (cx - 0.5f * rw) * SCALE;
    float x2s = (cx + 0.5f * rw) * SCALE;
    float y1s = (cy - 0.5f * rh) * SCALE;
    float y2s = (cy + 0.5f * rh) * SCALE;

    float roi_w = fmaxf(x2s - x1s, 1.0f);
    float roi_h = fmaxf(y2s - y1s, 1.0f);
    float bin_w = roi_w * (1.0f / PW);
    float bin_h = roi_h * (1.0f / PH);

    // base pointer with lane offset folded in; all tap offsets are 32-bit
    // byte offsets (table is 55.7 MB < 2^31).
    const char* tbl = reinterpret_cast<const char*>(g_nhwc) + lane * 16;

    #pragma unroll
    for (int i = 0; i < 2; i++) {
        int pw  = pwpair * 2 + i;
        int bin = ph_l * PW + pw;

        float a0=0.f,a1=0.f,a2=0.f,a3=0.f,a4=0.f,a5=0.f,a6=0.f,a7=0.f;

        unsigned xo0[2], xo1[2];     // x byte offsets (x * 512)
        float lx[2], hx[2];
        bool  vx[2];
        #pragma unroll
        for (int sx = 0; sx < 2; sx++) {
            float x = x1s + ((float)pw + ((float)sx + 0.5f) * 0.5f) * bin_w;
            vx[sx] = (x > -1.0f) && (x < (float)Wc);
            float xc = fminf(fmaxf(x, 0.0f), (float)(Wc - 1));
            int x0 = (int)floorf(xc);
            xo0[sx] = (unsigned)x0 << 9;
            xo1[sx] = (unsigned)min(x0 + 1, Wc - 1) << 9;
            lx[sx] = xc - (float)x0;
            hx[sx] = 1.0f - lx[sx];
        }

        // half2 tap: 1 cvt + 4 HFMA2, per-tap guard (R12, best measured)
        #define TAP(off, wt) do {                                               \
            if ((wt) != 0.0f) {                                                 \
                uint4 v = *reinterpret_cast<const uint4*>(tbl + (off));         \
                const __half2* hp = reinterpret_cast<const __half2*>(&v);       \
                __half2 wh = __float2half2_rn(wt);                              \
                h0 = __hfma2(wh, hp[0], h0);                                    \
                h1 = __hfma2(wh, hp[1], h1);                                    \
                h2 = __hfma2(wh, hp[2], h2);                                    \
                h3 = __hfma2(wh, hp[3], h3);                                    \
            }                                                                   \
        } while (0)

        #pragma unroll
        for (int sy = 0; sy < 2; sy++) {
            float y = y1s + ((float)ph + (sy ? 0.75f : 0.25f)) * bin_h;
            bool vy = (y > -1.0f) && (y < (float)Hc);
            float yc = fminf(fmaxf(y, 0.0f), (float)(Hc - 1));
            int y0 = (int)floorf(yc);
            int y1b = min(y0 + 1, Hc - 1);
            float ly = yc - (float)y0;
            float hy = 1.0f - ly;

            unsigned rb0 = (unsigned)((b * Hc + y0)  * Wc) << 9;  // row byte off
            unsigned rb1 = (unsigned)((b * Hc + y1b) * Wc) << 9;

            __half2 h0 = __float2half2_rn(0.f);
            __half2 h1 = h0, h2 = h0, h3 = h0;

            #pragma unroll
            for (int sx = 0; sx < 2; sx++) {
                float wq = (vy && vx[sx]) ? 0.25f : 0.0f;   // validity + mean
                float w00 = wq * hy * hx[sx];
                float w01 = wq * hy * lx[sx];
                float w10 = wq * ly * hx[sx];
                float w11 = wq * ly * lx[sx];
                TAP(rb0 + xo0[sx], w00);
                TAP(rb0 + xo1[sx], w01);
                TAP(rb1 + xo0[sx], w10);
                TAP(rb1 + xo1[sx], w11);
            }

            float2 f0 = __half22float2(h0);
            float2 f1 = __half22float2(h1);
            float2 f2 = __half22float2(h2);
            float2 f3 = __half22float2(h3);
            a0 += f0.x; a1 += f0.y;
            a2 += f1.x; a3 += f1.y;
            a4 += f2.x; a5 += f2.y;
            a6 += f3.x; a7 += f3.y;
        }
        #undef TAP

        float* dst = s + bin * SSTR + lane * 8;
        *reinterpret_cast<float4*>(dst)     = make_float4(a0, a1, a2, a3);
        *reinterpret_cast<float4*>(dst + 4) = make_float4(a4, a5, a6, a7);
    }

    __syncthreads();

    // epilogue: LDS.64 channel pairs (s row is 8B-aligned: SSTR even, c even),
    // two coalesced 28-float output runs per iteration.
    for (int c = 2 * wid; c < Cc; c += 28) {
        if (lane < BINS) {
            float2 v = *reinterpret_cast<const float2*>(&s[lane * SSTR + c]);
            size_t o = ((size_t)n * Cc + c) * (PH * PW) + php * BINS + lane;
            __stcs(out + o, v.x);
            __stcs(out + o + (PH * PW), v.y);
        }
    }
}

extern "C" void kernel_launch(void* const* d_in, const int* in_sizes, int n_in,
                              void* d_out, int out_size)
{
    const float* feat = (const float*)d_in[0];
    const float* rois = (const float*)d_in[1];
    float* out = (float*)d_out;

    int K = in_sizes[1] / 5;

    dim3 tg(Wc / 16, Hc, Bc);          // 17 x 200 x 2
    transpose_kernel<<<tg, 256>>>(feat);

    dim3 gg(K, PH / 2);                // K x 7
    gather_kernel<<<gg, 448>>>(rois, out);
}